// round 5
// baseline (speedup 1.0000x reference)
#include <cuda_runtime.h>
#include <math.h>

#define NN 50000
#define EE 400000
#define HH 5
#define CC 64
#define HC 320   // H*C
#define ED 16    // edge dim

// ---------------- scratch (device globals; no allocation allowed) ----------------
__device__ float g_sums[NN * ED];       // self-loop attr (mean of incoming edge attrs)
__device__ int   g_deg[NN + 1];         // in-degree (original edges)
__device__ int   g_rowptr[NN + 1];      // CSR row pointers (by dst)
__device__ int   g_cursor[NN];          // scatter cursors
__device__ int   g_csr_src[EE];         // src node per CSR slot
__device__ int   g_csr_eid[EE];         // original edge id per CSR slot
__device__ float g_h[NN * HC];          // per-layer transformed features [N,320]
__device__ float g_act[NN * CC];        // layer activations [N,64]

// ---------------- small helpers ----------------
__device__ __forceinline__ unsigned long long pack2(float a) {
    unsigned long long r;
    asm("mov.b64 %0,{%1,%1};" : "=l"(r) : "f"(a));
    return r;
}
__device__ __forceinline__ float2 up2(unsigned long long v) {
    float2 r;
    asm("mov.b64 {%0,%1},%2;" : "=f"(r.x), "=f"(r.y) : "l"(v));
    return r;
}
__device__ __forceinline__ void ffma2(unsigned long long& c, unsigned long long a,
                                      unsigned long long b) {
    asm("fma.rn.f32x2 %0,%1,%2,%0;" : "+l"(c) : "l"(a), "l"(b));
}
__device__ __forceinline__ float lrelu(float v) {
    return fmaxf(v, 0.0f) + 0.2f * fminf(v, 0.0f);
}

// e[h] (float2 for channels 2l,2l+1 of head h) = sum_k ea[k] * We[k][h*64 + 2l ..]
__device__ __forceinline__ void e_step(unsigned long long ev[HH], float a, const float* wb) {
    unsigned long long a2 = pack2(a);
#pragma unroll
    for (int h = 0; h < HH; h++) {
        unsigned long long w = *(const unsigned long long*)(wb + h * CC);
        ffma2(ev[h], a2, w);
    }
}
__device__ __forceinline__ void e_compute(unsigned long long ev[HH], const float4* eap,
                                          const float* We_s, int l) {
#pragma unroll
    for (int h = 0; h < HH; h++) ev[h] = 0ull;
    const float* wb = We_s + 2 * l;
#pragma unroll
    for (int q = 0; q < 4; q++) {
        float4 a = eap[q];
        e_step(ev, a.x, wb + (q * 4 + 0) * HC);
        e_step(ev, a.y, wb + (q * 4 + 1) * HC);
        e_step(ev, a.z, wb + (q * 4 + 2) * HC);
        e_step(ev, a.w, wb + (q * 4 + 3) * HC);
    }
}

// ---------------- setup kernels ----------------
__global__ void zero_kernel(int N) {
    int i = blockIdx.x * blockDim.x + threadIdx.x;
    if (i < N * ED) g_sums[i] = 0.0f;
    if (i <= N) g_deg[i] = 0;
}

__global__ void accum_kernel(const int* __restrict__ ei, const float* __restrict__ ea, int E) {
    int e = blockIdx.x * blockDim.x + threadIdx.x;
    if (e >= E) return;
    int d = ei[E + e];  // dst
    atomicAdd(&g_deg[d], 1);
    const float4* p = (const float4*)(ea + (size_t)e * ED);
    float* s = g_sums + (size_t)d * ED;
#pragma unroll
    for (int q = 0; q < 4; q++) {
        float4 v = p[q];
        atomicAdd(s + q * 4 + 0, v.x);
        atomicAdd(s + q * 4 + 1, v.y);
        atomicAdd(s + q * 4 + 2, v.z);
        atomicAdd(s + q * 4 + 3, v.w);
    }
}

__global__ void finalize_kernel(int N) {
    int i = blockIdx.x * blockDim.x + threadIdx.x;
    if (i >= N * ED) return;
    int n = i >> 4;
    int c = g_deg[n];
    if (c < 1) c = 1;
    g_sums[i] = g_sums[i] / (float)c;
}

__global__ void scan_kernel(int N) {
    __shared__ int sh_warp[32];
    __shared__ int sh_carry;
    int t = threadIdx.x;  // 1024 threads
    if (t == 0) sh_carry = 0;
    __syncthreads();
    for (int base = 0; base < N; base += 1024) {
        int i = base + t;
        int v = (i < N) ? g_deg[i] : 0;
        int incl = v;
#pragma unroll
        for (int o = 1; o < 32; o <<= 1) {
            int u = __shfl_up_sync(0xffffffffu, incl, o);
            if ((t & 31) >= o) incl += u;
        }
        if ((t & 31) == 31) sh_warp[t >> 5] = incl;
        __syncthreads();
        if (t < 32) {
            int w = sh_warp[t];
            int wi = w;
#pragma unroll
            for (int o = 1; o < 32; o <<= 1) {
                int u = __shfl_up_sync(0xffffffffu, wi, o);
                if (t >= o) wi += u;
            }
            sh_warp[t] = wi - w;  // exclusive warp offset
        }
        __syncthreads();
        int excl = sh_carry + sh_warp[t >> 5] + incl - v;
        if (i < N) {
            g_rowptr[i] = excl;
            g_cursor[i] = excl;
        }
        __syncthreads();
        if (t == 1023) sh_carry = excl + v;
        __syncthreads();
    }
    if (t == 0) g_rowptr[N] = sh_carry;
}

__global__ void scatter_kernel(const int* __restrict__ ei, int E) {
    int e = blockIdx.x * blockDim.x + threadIdx.x;
    if (e >= E) return;
    int s = ei[e];
    int d = ei[E + e];
    int pos = atomicAdd(&g_cursor[d], 1);
    g_csr_src[pos] = s;
    g_csr_eid[pos] = e;
}

// ---------------- GEMM: g_h[N,320] = A[N,K] @ W[K,320] + b ----------------
template <int K, bool USE_ACT>
__global__ void __launch_bounds__(256) gemm_kernel(const float* __restrict__ Ain,
                                                   const float* __restrict__ W,
                                                   const float* __restrict__ b, int N) {
    const float* A = USE_ACT ? (const float*)g_act : Ain;
    __shared__ float As[16][64];
    __shared__ float Ws[16][HC];
    int tid = threadIdx.x;
    int cg = tid & 31;   // column group: cols cg + 32*i, i<10
    int rg = tid >> 5;   // row group: rows rg*8 .. rg*8+7 (within 64-row block)
    int row0 = blockIdx.x * 64;

    float acc[8][10];
#pragma unroll
    for (int r = 0; r < 8; r++)
#pragma unroll
        for (int i = 0; i < 10; i++) acc[r][i] = 0.0f;

    for (int kc = 0; kc < K; kc += 16) {
        {   // stage A chunk (transposed): As[k][r] = A[row0+r][kc+k]
            int r = tid >> 2;
            int kk = (tid & 3) * 4;
            int row = row0 + r;
            float4 v = make_float4(0.f, 0.f, 0.f, 0.f);
            if (row < N) v = *(const float4*)(A + (size_t)row * K + kc + kk);
            As[kk + 0][r] = v.x;
            As[kk + 1][r] = v.y;
            As[kk + 2][r] = v.z;
            As[kk + 3][r] = v.w;
        }
        {   // stage W chunk: 16 x 320 = 1280 float4
            const float4* Wv = (const float4*)(W + (size_t)kc * HC);
            float4* Wsv = (float4*)&Ws[0][0];
#pragma unroll
            for (int i = 0; i < 5; i++) Wsv[i * 256 + tid] = Wv[i * 256 + tid];
        }
        __syncthreads();
#pragma unroll
        for (int k = 0; k < 16; k++) {
            float4 a0 = *(const float4*)&As[k][rg * 8];
            float4 a1 = *(const float4*)&As[k][rg * 8 + 4];
            float a[8] = {a0.x, a0.y, a0.z, a0.w, a1.x, a1.y, a1.z, a1.w};
            float w[10];
#pragma unroll
            for (int i = 0; i < 10; i++) w[i] = Ws[k][cg + 32 * i];
#pragma unroll
            for (int r = 0; r < 8; r++)
#pragma unroll
                for (int i = 0; i < 10; i++) acc[r][i] = fmaf(a[r], w[i], acc[r][i]);
        }
        __syncthreads();
    }
    float bb[10];
#pragma unroll
    for (int i = 0; i < 10; i++) bb[i] = b[cg + 32 * i];
#pragma unroll
    for (int r = 0; r < 8; r++) {
        int row = row0 + rg * 8 + r;
        if (row < N) {
            float* hp = g_h + (size_t)row * HC + cg;
#pragma unroll
            for (int i = 0; i < 10; i++) hp[32 * i] = acc[r][i] + bb[i];
        }
    }
}

// ---------------- attention: one warp per dst node, online softmax ----------------
__global__ void __launch_bounds__(256) attn_kernel(const float* __restrict__ edge_attr,
                                                   const float* __restrict__ We,
                                                   const float* __restrict__ att,
                                                   const float* __restrict__ bias,
                                                   float* __restrict__ outp, int N,
                                                   int use_act_out) {
    __shared__ float We_s[ED * HC];  // 20KB
    {
        const float4* s4 = (const float4*)We;
        float4* d4 = (float4*)We_s;
        for (int i = threadIdx.x; i < (ED * HC) / 4; i += 256) d4[i] = s4[i];
    }
    __syncthreads();

    int warp = threadIdx.x >> 5;
    int l = threadIdx.x & 31;
    int n = blockIdx.x * 8 + warp;
    if (n >= N) return;

    const float* hrow_d = g_h + (size_t)n * HC;
    float2 hd[HH], at2[HH];
#pragma unroll
    for (int h = 0; h < HH; h++) {
        hd[h] = *(const float2*)(hrow_d + h * CC + 2 * l);
        at2[h] = *(const float2*)(att + h * CC + 2 * l);
    }

    float m5[HH], d5[HH];
    float2 acc[HH];

    // ---- self loop (src == dst, attr = mean of incoming attrs) ----
    {
        const float4* eap = (const float4*)(g_sums + (size_t)n * ED);
        unsigned long long ev[HH];
        e_compute(ev, eap, We_s, l);
        float p5[HH];
#pragma unroll
        for (int h = 0; h < HH; h++) {
            float2 e2 = up2(ev[h]);
            float vx = 2.0f * hd[h].x + e2.x;
            float vy = 2.0f * hd[h].y + e2.y;
            p5[h] = fmaf(lrelu(vx), at2[h].x, lrelu(vy) * at2[h].y);
        }
#pragma unroll
        for (int off = 16; off > 0; off >>= 1) {
#pragma unroll
            for (int h = 0; h < HH; h++) p5[h] += __shfl_xor_sync(0xffffffffu, p5[h], off);
        }
#pragma unroll
        for (int h = 0; h < HH; h++) {
            m5[h] = p5[h];
            d5[h] = 1.0f;    // exp(logit - m) = 1
            acc[h] = hd[h];  // 1 * h_src (== h_dst)
        }
    }

    // ---- incoming edges ----
    int beg = g_rowptr[n];
    int end = g_rowptr[n + 1];
    for (int j = beg; j < end; j++) {
        int src = g_csr_src[j];
        int eid = g_csr_eid[j];
        const float* hrow_s = g_h + (size_t)src * HC;
        float2 hs[HH];
#pragma unroll
        for (int h = 0; h < HH; h++) hs[h] = *(const float2*)(hrow_s + h * CC + 2 * l);
        const float4* eap = (const float4*)(edge_attr + (size_t)eid * ED);
        unsigned long long ev[HH];
        e_compute(ev, eap, We_s, l);
        float p5[HH];
#pragma unroll
        for (int h = 0; h < HH; h++) {
            float2 e2 = up2(ev[h]);
            float vx = hs[h].x + hd[h].x + e2.x;
            float vy = hs[h].y + hd[h].y + e2.y;
            p5[h] = fmaf(lrelu(vx), at2[h].x, lrelu(vy) * at2[h].y);
        }
#pragma unroll
        for (int off = 16; off > 0; off >>= 1) {
#pragma unroll
            for (int h = 0; h < HH; h++) p5[h] += __shfl_xor_sync(0xffffffffu, p5[h], off);
        }
#pragma unroll
        for (int h = 0; h < HH; h++) {
            float mn = fmaxf(m5[h], p5[h]);
            float sc = __expf(m5[h] - mn);
            float pe = __expf(p5[h] - mn);
            d5[h] = d5[h] * sc + pe;
            acc[h].x = fmaf(pe, hs[h].x, acc[h].x * sc);
            acc[h].y = fmaf(pe, hs[h].y, acc[h].y * sc);
            m5[h] = mn;
        }
    }

    // ---- epilogue: head mean + bias + ELU ----
    float ox = 0.0f, oy = 0.0f;
#pragma unroll
    for (int h = 0; h < HH; h++) {
        float inv = 1.0f / (d5[h] + 1e-16f);
        ox = fmaf(acc[h].x, inv, ox);
        oy = fmaf(acc[h].y, inv, oy);
    }
    ox *= 0.2f;  // 1/H
    oy *= 0.2f;
    float2 bv = *(const float2*)(bias + 2 * l);
    ox += bv.x;
    oy += bv.y;
    ox = (ox > 0.0f) ? ox : expm1f(ox);
    oy = (oy > 0.0f) ? oy : expm1f(oy);
    float* dst = use_act_out ? (g_act + (size_t)n * CC) : (outp + (size_t)n * CC);
    float2 o;
    o.x = ox;
    o.y = oy;
    *(float2*)(dst + 2 * l) = o;
}

// ---------------- launch ----------------
extern "C" void kernel_launch(void* const* d_in, const int* in_sizes, int n_in, void* d_out,
                              int out_size) {
    const float* x     = (const float*)d_in[0];
    const int*   ei    = (const int*)d_in[1];
    const float* ea    = (const float*)d_in[2];
    const float* W0    = (const float*)d_in[3];
    const float* b0    = (const float*)d_in[4];
    const float* We0   = (const float*)d_in[5];
    const float* att0  = (const float*)d_in[6];
    const float* bi0   = (const float*)d_in[7];
    const float* W12   = (const float*)d_in[8];
    const float* b12   = (const float*)d_in[9];
    const float* We12  = (const float*)d_in[10];
    const float* att12 = (const float*)d_in[11];
    const float* bi12  = (const float*)d_in[12];
    float* out = (float*)d_out;

    int N = in_sizes[0] / 128;
    int E = in_sizes[1] / 2;

    // setup: self-loop attrs + CSR by dst
    zero_kernel<<<(N * ED + 255) / 256, 256>>>(N);
    accum_kernel<<<(E + 255) / 256, 256>>>(ei, ea, E);
    finalize_kernel<<<(N * ED + 255) / 256, 256>>>(N);
    scan_kernel<<<1, 1024>>>(N);
    scatter_kernel<<<(E + 255) / 256, 256>>>(ei, E);

    int gb = (N + 63) / 64;
    int ab = (N + 7) / 8;

    // layer 0
    gemm_kernel<128, false><<<gb, 256>>>(x, W0, b0, N);
    attn_kernel<<<ab, 256>>>(ea, We0, att0, bi0, nullptr, N, 1);
    // layer 1 (index 0 of the *12 stacks)
    gemm_kernel<64, true><<<gb, 256>>>(nullptr, W12, b12, N);
    attn_kernel<<<ab, 256>>>(ea, We12, att12, bi12, nullptr, N, 1);
    // layer 2 (index 1 of the *12 stacks)
    gemm_kernel<64, true><<<gb, 256>>>(nullptr, W12 + 64 * HC, b12 + HC, N);
    attn_kernel<<<ab, 256>>>(ea, We12 + ED * HC, att12 + HH * CC, bi12 + CC, out, N, 0);
}

// round 6
// speedup vs baseline: 1.2546x; 1.2546x over previous
#include <cuda_runtime.h>
#include <math.h>

#define NN 50000
#define EE 400000
#define HH 5
#define CC 64
#define HC 320   // H*C
#define ED 16    // edge dim

typedef unsigned long long ull;

// ---------------- scratch (device globals; no allocation allowed) ----------------
__device__ float g_sums[NN * ED];       // self-loop attr (mean of incoming edge attrs)
__device__ int   g_deg[NN];             // in-degree (original edges)
__device__ int   g_rowptr[NN + 1];      // CSR row pointers (by dst)
__device__ int   g_cursor[NN];          // scatter cursors
__device__ int   g_bsum[64];            // block sums for scan
__device__ int2  g_csr[EE];             // (src, eid) per CSR slot
__device__ float g_h[NN * HC];          // per-layer transformed features [N,320]
__device__ float g_act[NN * CC];        // layer activations [N,64]

// ---------------- packed f32x2 helpers ----------------
__device__ __forceinline__ ull pack2(float a) {
    ull r;
    asm("mov.b64 %0,{%1,%1};" : "=l"(r) : "f"(a));
    return r;
}
__device__ __forceinline__ float2 up2(ull v) {
    float2 r;
    asm("mov.b64 {%0,%1},%2;" : "=f"(r.x), "=f"(r.y) : "l"(v));
    return r;
}
__device__ __forceinline__ void ffma2(ull& c, ull a, ull b) {
    asm("fma.rn.f32x2 %0,%1,%2,%0;" : "+l"(c) : "l"(a), "l"(b));
}
__device__ __forceinline__ ull add2(ull a, ull b) {
    ull r;
    asm("add.rn.f32x2 %0,%1,%2;" : "=l"(r) : "l"(a), "l"(b));
    return r;
}

// ---------------- setup kernels ----------------
__global__ void zero_deg_kernel(int N) {
    int i = blockIdx.x * blockDim.x + threadIdx.x;
    if (i < N) g_deg[i] = 0;
}

__global__ void deg_kernel(const int* __restrict__ ei, int E) {
    int e = blockIdx.x * blockDim.x + threadIdx.x;
    if (e >= E) return;
    atomicAdd(&g_deg[ei[E + e]], 1);
}

// phase A: per-1024 block scan, local exclusive into rowptr, block totals into g_bsum
__global__ void scan_a_kernel(int N) {
    __shared__ int sw[32];
    int t = threadIdx.x, lane = t & 31, wid = t >> 5;
    int i = blockIdx.x * 1024 + t;
    int v = (i < N) ? g_deg[i] : 0;
    int incl = v;
#pragma unroll
    for (int o = 1; o < 32; o <<= 1) {
        int u = __shfl_up_sync(0xffffffffu, incl, o);
        if (lane >= o) incl += u;
    }
    if (lane == 31) sw[wid] = incl;
    __syncthreads();
    if (t < 32) {
        int w = sw[t], s = w;
#pragma unroll
        for (int o = 1; o < 32; o <<= 1) {
            int u = __shfl_up_sync(0xffffffffu, s, o);
            if (t >= o) s += u;
        }
        sw[t] = s - w;
    }
    __syncthreads();
    int excl = sw[wid] + incl - v;
    if (i < N) g_rowptr[i] = excl;
    if (t == 1023) g_bsum[blockIdx.x] = excl + v;
}

// phase B: exclusive scan of block sums (nb <= 64), one block of 64 threads
__global__ void scan_b_kernel(int nb) {
    __shared__ int w0;
    int t = threadIdx.x;
    int v = (t < nb) ? g_bsum[t] : 0;
    int incl = v;
#pragma unroll
    for (int o = 1; o < 32; o <<= 1) {
        int u = __shfl_up_sync(0xffffffffu, incl, o);
        if ((t & 31) >= o) incl += u;
    }
    if (t == 31) w0 = incl;
    __syncthreads();
    int excl = incl - v + ((t >= 32) ? w0 : 0);
    g_bsum[t] = excl;
}

// phase C: add block offsets, init cursors, set rowptr[N]
__global__ void scan_c_kernel(int N, int E) {
    int i = blockIdx.x * blockDim.x + threadIdx.x;
    if (i < N) {
        int r = g_rowptr[i] + g_bsum[i >> 10];
        g_rowptr[i] = r;
        g_cursor[i] = r;
    }
    if (i == 0) g_rowptr[N] = E;
}

__global__ void scatter_kernel(const int* __restrict__ ei, int E) {
    int e = blockIdx.x * blockDim.x + threadIdx.x;
    if (e >= E) return;
    int s = ei[e];
    int d = ei[E + e];
    int pos = atomicAdd(&g_cursor[d], 1);
    g_csr[pos] = make_int2(s, e);
}

// self-loop attrs: mean of incoming edge attrs per node (atomic-free, CSR gather)
__global__ void __launch_bounds__(256) sums_kernel(const float* __restrict__ ea, int N) {
    int t = threadIdx.x;
    int n = blockIdx.x * 16 + (t >> 4);
    int c = t & 15;
    if (n >= N) return;
    int beg = g_rowptr[n], end = g_rowptr[n + 1];
    float s = 0.0f;
    for (int j = beg; j < end; j++) {
        int eid = g_csr[j].y;
        s += ea[(size_t)eid * ED + c];
    }
    int d = end - beg;
    if (d < 1) d = 1;
    g_sums[(size_t)n * ED + c] = s / (float)d;
}

// ---------------- GEMM: g_h[N,320] = A[N,K] @ W[K,320] + b  (f32x2 MACs) ----------------
template <int K, bool USE_ACT>
__global__ void __launch_bounds__(256) gemm_kernel(const float* __restrict__ Ain,
                                                   const float* __restrict__ W,
                                                   const float* __restrict__ b, int N) {
    const float* A = USE_ACT ? (const float*)g_act : Ain;
    __shared__ float As[16][64];
    __shared__ float Ws[16][HC];
    int tid = threadIdx.x;
    int cg = tid & 31;   // lane: column pairs (2cg + 64i, +1), i<5
    int rg = tid >> 5;   // warp: rows rg*8 .. rg*8+7 within 64-row block
    int row0 = blockIdx.x * 64;

    ull acc2[8][5];
#pragma unroll
    for (int r = 0; r < 8; r++)
#pragma unroll
        for (int i = 0; i < 5; i++) acc2[r][i] = 0ull;

    for (int kc = 0; kc < K; kc += 16) {
        {   // stage A chunk (transposed): As[k][r] = A[row0+r][kc+k]
            int r = tid >> 2;
            int kk = (tid & 3) * 4;
            int row = row0 + r;
            float4 v = make_float4(0.f, 0.f, 0.f, 0.f);
            if (row < N) v = *(const float4*)(A + (size_t)row * K + kc + kk);
            As[kk + 0][r] = v.x;
            As[kk + 1][r] = v.y;
            As[kk + 2][r] = v.z;
            As[kk + 3][r] = v.w;
        }
        {   // stage W chunk: 16 x 320 = 1280 float4
            const float4* Wv = (const float4*)(W + (size_t)kc * HC);
            float4* Wsv = (float4*)&Ws[0][0];
#pragma unroll
            for (int i = 0; i < 5; i++) Wsv[i * 256 + tid] = Wv[i * 256 + tid];
        }
        __syncthreads();
#pragma unroll
        for (int k = 0; k < 16; k++) {
            float4 a0 = *(const float4*)&As[k][rg * 8];
            float4 a1 = *(const float4*)&As[k][rg * 8 + 4];
            ull a2[8] = {pack2(a0.x), pack2(a0.y), pack2(a0.z), pack2(a0.w),
                         pack2(a1.x), pack2(a1.y), pack2(a1.z), pack2(a1.w)};
            ull w2[5];
#pragma unroll
            for (int i = 0; i < 5; i++) w2[i] = *(const ull*)&Ws[k][2 * cg + 64 * i];
#pragma unroll
            for (int r = 0; r < 8; r++)
#pragma unroll
                for (int i = 0; i < 5; i++) ffma2(acc2[r][i], a2[r], w2[i]);
        }
        __syncthreads();
    }
    float2 bb[5];
#pragma unroll
    for (int i = 0; i < 5; i++) bb[i] = *(const float2*)(b + 2 * cg + 64 * i);
#pragma unroll
    for (int r = 0; r < 8; r++) {
        int row = row0 + rg * 8 + r;
        if (row < N) {
            float* hp = g_h + (size_t)row * HC + 2 * cg;
#pragma unroll
            for (int i = 0; i < 5; i++) {
                float2 v = up2(acc2[r][i]);
                v.x += bb[i].x;
                v.y += bb[i].y;
                *(float2*)(hp + 64 * i) = v;
            }
        }
    }
}

// ---------------- attention: warp per dst, pair-unrolled edges, no-max softmax ----------------
__global__ void __launch_bounds__(128) attn_kernel(const float* __restrict__ edge_attr,
                                                   const float* __restrict__ We,
                                                   const float* __restrict__ att,
                                                   const float* __restrict__ bias,
                                                   float* __restrict__ outp, int N,
                                                   int use_act_out) {
    __shared__ float We_s[ED * HC];  // 20KB
    {
        const float4* s4 = (const float4*)We;
        float4* d4 = (float4*)We_s;
        for (int i = threadIdx.x; i < (ED * HC) / 4; i += 128) d4[i] = s4[i];
    }
    __syncthreads();

    int l = threadIdx.x & 31;
    int n = blockIdx.x * 4 + (threadIdx.x >> 5);
    if (n >= N) return;

    ull hdp[5];
    float2 at2[5];
    const float* hrd = g_h + (size_t)n * HC + 2 * l;
#pragma unroll
    for (int h = 0; h < HH; h++) {
        hdp[h] = *(const ull*)(hrd + h * CC);
        at2[h] = *(const float2*)(att + h * CC + 2 * l);
    }
    float d5[5];
    float2 acc[5];
#pragma unroll
    for (int h = 0; h < HH; h++) {
        d5[h] = 0.0f;
        acc[h] = make_float2(0.0f, 0.0f);
    }
    const float* wb = We_s + 2 * l;

    // ---- self loop: v = 2*hd + e(loop_attr) ----
    {
        ull ev[5];
#pragma unroll
        for (int h = 0; h < HH; h++) ev[h] = add2(hdp[h], hdp[h]);
        const float4* sp = (const float4*)(g_sums + (size_t)n * ED);
#pragma unroll
        for (int q = 0; q < 4; q++) {
            float4 a = sp[q];
            float av[4] = {a.x, a.y, a.z, a.w};
#pragma unroll
            for (int s = 0; s < 4; s++) {
                int k = q * 4 + s;
                ull a2 = pack2(av[s]);
#pragma unroll
                for (int h = 0; h < HH; h++) {
                    ull w = *(const ull*)(wb + k * HC + h * CC);
                    ffma2(ev[h], a2, w);
                }
            }
        }
        float p5[5];
#pragma unroll
        for (int h = 0; h < HH; h++) {
            float2 v = up2(ev[h]);
            float lx = fmaf(0.2f, fminf(v.x, 0.f), fmaxf(v.x, 0.f));
            float ly = fmaf(0.2f, fminf(v.y, 0.f), fmaxf(v.y, 0.f));
            p5[h] = fmaf(lx, at2[h].x, ly * at2[h].y);
        }
#pragma unroll
        for (int o = 16; o > 0; o >>= 1)
#pragma unroll
            for (int h = 0; h < HH; h++) p5[h] += __shfl_xor_sync(0xffffffffu, p5[h], o);
#pragma unroll
        for (int h = 0; h < HH; h++) {
            float pe = __expf(fminf(p5[h], 80.0f));
            float2 hv = up2(hdp[h]);
            d5[h] += pe;
            acc[h].x = fmaf(pe, hv.x, acc[h].x);
            acc[h].y = fmaf(pe, hv.y, acc[h].y);
        }
    }

    // ---- incoming edges, processed in pairs sharing the We smem loads ----
    int beg = g_rowptr[n], end = g_rowptr[n + 1];
    for (int j = beg; j < end; j += 2) {
        bool two = (j + 1 < end);
        int2 seA = g_csr[j];
        int2 seB = g_csr[two ? j + 1 : j];

        float4 eaA[4], eaB[4];
        ull hsA[5], hsB[5];
        const float4* epA = (const float4*)(edge_attr + (size_t)seA.y * ED);
        const float4* epB = (const float4*)(edge_attr + (size_t)seB.y * ED);
#pragma unroll
        for (int q = 0; q < 4; q++) {
            eaA[q] = epA[q];
            eaB[q] = epB[q];
        }
        const float* hpA = g_h + (size_t)seA.x * HC + 2 * l;
        const float* hpB = g_h + (size_t)seB.x * HC + 2 * l;
#pragma unroll
        for (int h = 0; h < HH; h++) {
            hsA[h] = *(const ull*)(hpA + h * CC);
            hsB[h] = *(const ull*)(hpB + h * CC);
        }

        ull evA[5], evB[5];
#pragma unroll
        for (int h = 0; h < HH; h++) {
            evA[h] = add2(hsA[h], hdp[h]);
            evB[h] = add2(hsB[h], hdp[h]);
        }
#pragma unroll
        for (int q = 0; q < 4; q++) {
            float avA[4] = {eaA[q].x, eaA[q].y, eaA[q].z, eaA[q].w};
            float avB[4] = {eaB[q].x, eaB[q].y, eaB[q].z, eaB[q].w};
#pragma unroll
            for (int s = 0; s < 4; s++) {
                int k = q * 4 + s;
                ull a2A = pack2(avA[s]);
                ull a2B = pack2(avB[s]);
#pragma unroll
                for (int h = 0; h < HH; h++) {
                    ull w = *(const ull*)(wb + k * HC + h * CC);  // one LDS serves both edges
                    ffma2(evA[h], a2A, w);
                    ffma2(evB[h], a2B, w);
                }
            }
        }

        // finish edge A
        {
            float p5[5];
#pragma unroll
            for (int h = 0; h < HH; h++) {
                float2 v = up2(evA[h]);
                float lx = fmaf(0.2f, fminf(v.x, 0.f), fmaxf(v.x, 0.f));
                float ly = fmaf(0.2f, fminf(v.y, 0.f), fmaxf(v.y, 0.f));
                p5[h] = fmaf(lx, at2[h].x, ly * at2[h].y);
            }
#pragma unroll
            for (int o = 16; o > 0; o >>= 1)
#pragma unroll
                for (int h = 0; h < HH; h++) p5[h] += __shfl_xor_sync(0xffffffffu, p5[h], o);
#pragma unroll
            for (int h = 0; h < HH; h++) {
                float pe = __expf(fminf(p5[h], 80.0f));
                float2 hv = up2(hsA[h]);
                d5[h] += pe;
                acc[h].x = fmaf(pe, hv.x, acc[h].x);
                acc[h].y = fmaf(pe, hv.y, acc[h].y);
            }
        }
        // finish edge B (if valid)
        if (two) {
            float p5[5];
#pragma unroll
            for (int h = 0; h < HH; h++) {
                float2 v = up2(evB[h]);
                float lx = fmaf(0.2f, fminf(v.x, 0.f), fmaxf(v.x, 0.f));
                float ly = fmaf(0.2f, fminf(v.y, 0.f), fmaxf(v.y, 0.f));
                p5[h] = fmaf(lx, at2[h].x, ly * at2[h].y);
            }
#pragma unroll
            for (int o = 16; o > 0; o >>= 1)
#pragma unroll
                for (int h = 0; h < HH; h++) p5[h] += __shfl_xor_sync(0xffffffffu, p5[h], o);
#pragma unroll
            for (int h = 0; h < HH; h++) {
                float pe = __expf(fminf(p5[h], 80.0f));
                float2 hv = up2(hsB[h]);
                d5[h] += pe;
                acc[h].x = fmaf(pe, hv.x, acc[h].x);
                acc[h].y = fmaf(pe, hv.y, acc[h].y);
            }
        }
    }

    // ---- epilogue: head mean + bias + ELU ----
    float ox = 0.0f, oy = 0.0f;
#pragma unroll
    for (int h = 0; h < HH; h++) {
        float inv = __fdividef(1.0f, d5[h]);
        ox = fmaf(acc[h].x, inv, ox);
        oy = fmaf(acc[h].y, inv, oy);
    }
    ox *= 0.2f;  // 1/H
    oy *= 0.2f;
    float2 bv = *(const float2*)(bias + 2 * l);
    ox += bv.x;
    oy += bv.y;
    ox = (ox > 0.0f) ? ox : expm1f(ox);
    oy = (oy > 0.0f) ? oy : expm1f(oy);
    float* dst = use_act_out ? (g_act + (size_t)n * CC) : (outp + (size_t)n * CC);
    *(float2*)(dst + 2 * l) = make_float2(ox, oy);
}

// ---------------- launch ----------------
extern "C" void kernel_launch(void* const* d_in, const int* in_sizes, int n_in, void* d_out,
                              int out_size) {
    const float* x     = (const float*)d_in[0];
    const int*   ei    = (const int*)d_in[1];
    const float* ea    = (const float*)d_in[2];
    const float* W0    = (const float*)d_in[3];
    const float* b0    = (const float*)d_in[4];
    const float* We0   = (const float*)d_in[5];
    const float* att0  = (const float*)d_in[6];
    const float* bi0   = (const float*)d_in[7];
    const float* W12   = (const float*)d_in[8];
    const float* b12   = (const float*)d_in[9];
    const float* We12  = (const float*)d_in[10];
    const float* att12 = (const float*)d_in[11];
    const float* bi12  = (const float*)d_in[12];
    float* out = (float*)d_out;

    int N = in_sizes[0] / 128;
    int E = in_sizes[1] / 2;
    int nb = (N + 1023) / 1024;

    // setup: degrees -> parallel scan -> CSR scatter -> self-loop mean attrs
    zero_deg_kernel<<<(N + 255) / 256, 256>>>(N);
    deg_kernel<<<(E + 255) / 256, 256>>>(ei, E);
    scan_a_kernel<<<nb, 1024>>>(N);
    scan_b_kernel<<<1, 64>>>(nb);
    scan_c_kernel<<<(N + 255) / 256, 256>>>(N, E);
    scatter_kernel<<<(E + 255) / 256, 256>>>(ei, E);
    sums_kernel<<<(N + 15) / 16, 256>>>(ea, N);

    int gb = (N + 63) / 64;
    int ab = (N + 3) / 4;

    // layer 0
    gemm_kernel<128, false><<<gb, 256>>>(x, W0, b0, N);
    attn_kernel<<<ab, 128>>>(ea, We0, att0, bi0, nullptr, N, 1);
    // layer 1
    gemm_kernel<64, true><<<gb, 256>>>(nullptr, W12, b12, N);
    attn_kernel<<<ab, 128>>>(ea, We12, att12, bi12, nullptr, N, 1);
    // layer 2
    gemm_kernel<64, true><<<gb, 256>>>(nullptr, W12 + 64 * HC, b12 + HC, N);
    attn_kernel<<<ab, 128>>>(ea, We12 + ED * HC, att12 + HH * CC, bi12 + CC, out, N, 0);
}